// round 1
// baseline (speedup 1.0000x reference)
#include <cuda_runtime.h>
#include <math.h>

#define B 8
#define OUTD 592002

// ---------------- scratch (device globals; no allocation allowed) ----------------
__device__ float g_bufA[(size_t)B * 128 * 256 * 256];   // 268 MB ping
__device__ float g_bufB[(size_t)B * 128 * 256 * 256];   // 268 MB pong
__device__ float g_skip1[(size_t)B * 64 * 256 * 256];   // conv1 output
__device__ float g_skip2[(size_t)B * 64 * 128 * 128];   // conv2 output
__device__ float g_skip3[(size_t)B * 64 * 64 * 64];     // conv3 output
__device__ float g_w[(size_t)B * OUTD];                 // generated weights
__device__ float g_h2[B * 32];                          // hypernet hidden

// ---------------- hypernet stage 1: h2 = (hp@W1^T+b1)@W2^T+b2 ----------------
__global__ void hyper1_kernel(const float* __restrict__ hp, const float* __restrict__ W1,
                              const float* __restrict__ b1, const float* __restrict__ W2,
                              const float* __restrict__ b2)
{
    __shared__ float h1[B][32];
    int b = threadIdx.x >> 5;
    int i = threadIdx.x & 31;
    // IN_DIM = 1: h1[b][i] = hp[b]*W1[i][0] + b1[i]
    h1[b][i] = hp[b] * W1[i] + b1[i];
    __syncthreads();
    float a = b2[i];
#pragma unroll
    for (int k = 0; k < 32; k++) a += h1[b][k] * W2[i * 32 + k];
    g_h2[b * 32 + i] = a;
}

__global__ void zero_l1_kernel(float* __restrict__ l1)
{
    if (threadIdx.x < B) l1[threadIdx.x] = 0.f;
}

// ---------------- hypernet stage 2: w = tanh(h2 @ Wo^T + bo), + L1 reduce ----------------
__global__ void weightgen_kernel(const float* __restrict__ Wo, const float* __restrict__ bo,
                                 float* __restrict__ l1out)
{
    __shared__ float sh2[B * 32];
    __shared__ float wsum[8][B];
    int tid = threadIdx.x;
    sh2[tid] = g_h2[tid];   // 256 floats, 256 threads
    __syncthreads();

    int j = blockIdx.x * 256 + tid;
    float s[B];
#pragma unroll
    for (int b = 0; b < B; b++) s[b] = 0.f;

    if (j < OUTD) {
        float wr[32];
        const float* row = Wo + (size_t)j * 32;
#pragma unroll
        for (int i = 0; i < 32; i++) wr[i] = row[i];
        float bj = bo[j];
#pragma unroll
        for (int b = 0; b < B; b++) {
            float a = bj;
#pragma unroll
            for (int i = 0; i < 32; i++) a += wr[i] * sh2[b * 32 + i];
            float w = tanhf(a);
            g_w[(size_t)b * OUTD + j] = w;
            s[b] = fabsf(w);
        }
    }
    // warp reduce each of the 8 partials
    int warp = tid >> 5, lane = tid & 31;
#pragma unroll
    for (int b = 0; b < B; b++) {
        float v = s[b];
        for (int off = 16; off > 0; off >>= 1) v += __shfl_xor_sync(0xFFFFFFFFu, v, off);
        if (lane == 0) wsum[warp][b] = v;
    }
    __syncthreads();
    if (tid < B) {
        float a = 0.f;
#pragma unroll
        for (int w = 0; w < 8; w++) a += wsum[w][tid];
        atomicAdd(&l1out[tid], a);
    }
}

// ---------------- NHWC zf -> NCHW x0 ----------------
__global__ void transpose_in_kernel(const float* __restrict__ zf, float* __restrict__ out)
{
    int idx = blockIdx.x * blockDim.x + threadIdx.x;   // over B*2*256*256
    int total = B * 2 * 256 * 256;
    if (idx >= total) return;
    int w = idx & 255;
    int h = (idx >> 8) & 255;
    int c = (idx >> 16) & 1;
    int b = idx >> 17;
    out[idx] = zf[(((b * 256 + h) * 256 + w) << 1) + c];
}

// ---------------- generic 3x3 conv, pad=1, OC=64, per-sample weights ----------------
template<int CIN>
__global__ __launch_bounds__(256) void conv3x3_kernel(
    const float* __restrict__ in, float* __restrict__ out,
    const float* __restrict__ wbuf, int woff, int boff, int H, int W, int relu)
{
    __shared__ float sIn[18 * 18];
    __shared__ float sW[16 * 9];
    int b   = blockIdx.z;
    int ocg = blockIdx.y;
    int tilesX = W >> 4;
    int tx0 = (blockIdx.x % tilesX) << 4;
    int ty0 = (blockIdx.x / tilesX) << 4;
    int tx = threadIdx.x, ty = threadIdx.y;
    int tid = ty * 16 + tx;
    const float* wb  = wbuf + (size_t)b * OUTD;
    const float* inb = in + (size_t)b * CIN * H * W;

    float acc[16];
#pragma unroll
    for (int i = 0; i < 16; i++) acc[i] = 0.f;

    for (int c = 0; c < CIN; c++) {
        __syncthreads();
        // haloed 18x18 input tile for channel c
        for (int idx = tid; idx < 324; idx += 256) {
            int iy = idx / 18, ix = idx - iy * 18;
            int gy = ty0 - 1 + iy, gx = tx0 - 1 + ix;
            float v = 0.f;
            if (gy >= 0 && gy < H && gx >= 0 && gx < W)
                v = inb[(size_t)c * H * W + gy * W + gx];
            sIn[idx] = v;
        }
        if (tid < 144) {
            int oc = tid / 9, k = tid - oc * 9;
            sW[tid] = wb[woff + ((ocg * 16 + oc) * CIN + c) * 9 + k];
        }
        __syncthreads();
        float r[9];
#pragma unroll
        for (int dy = 0; dy < 3; dy++)
#pragma unroll
            for (int dx = 0; dx < 3; dx++)
                r[dy * 3 + dx] = sIn[(ty + dy) * 18 + (tx + dx)];
#pragma unroll
        for (int i = 0; i < 16; i++) {
            float a = acc[i];
#pragma unroll
            for (int k = 0; k < 9; k++) a = fmaf(r[k], sW[i * 9 + k], a);
            acc[i] = a;
        }
    }
    int y = ty0 + ty, x = tx0 + tx;
#pragma unroll
    for (int i = 0; i < 16; i++) {
        int oc = ocg * 16 + i;
        float v = acc[i] + wb[boff + oc];
        if (relu) v = fmaxf(v, 0.f);
        out[(((size_t)b * 64 + oc) * H + y) * W + x] = v;
    }
}

// ---------------- 2x2 maxpool ----------------
__global__ void maxpool_kernel(const float* __restrict__ in, float* __restrict__ out, int H, int W)
{
    int Ho = H >> 1, Wo = W >> 1;
    int total = B * 64 * Ho * Wo;
    int idx = blockIdx.x * blockDim.x + threadIdx.x;
    if (idx >= total) return;
    int xo = idx % Wo;
    int yo = (idx / Wo) % Ho;
    int bc = idx / (Wo * Ho);
    const float* p = in + (size_t)bc * H * W + (yo * 2) * W + xo * 2;
    float v = fmaxf(fmaxf(p[0], p[1]), fmaxf(p[W], p[W + 1]));
    out[idx] = v;
}

// ---------------- bilinear upsample x2 (align_corners=True) into concat buffer ch 0..63 ----------------
__global__ void upsample_kernel(const float* __restrict__ in, float* __restrict__ out, int H, int W)
{
    int Ho = H * 2, Wo = W * 2;
    int total = B * 64 * Ho * Wo;
    int idx = blockIdx.x * blockDim.x + threadIdx.x;
    if (idx >= total) return;
    int xo = idx % Wo;
    int yo = (idx / Wo) % Ho;
    int c  = (idx / (Wo * Ho)) % 64;
    int b  = idx / (Wo * Ho * 64);

    float ys = (float)yo * (float)(H - 1) / (float)(Ho - 1);
    float xs = (float)xo * (float)(W - 1) / (float)(Wo - 1);
    int y0 = (int)floorf(ys); int y1 = min(y0 + 1, H - 1);
    int x0 = (int)floorf(xs); int x1 = min(x0 + 1, W - 1);
    float wy = ys - (float)y0, wx = xs - (float)x0;

    const float* p = in + ((size_t)b * 64 + c) * H * W;
    float r0 = p[y0 * W + x0] * (1.f - wy) + p[y1 * W + x0] * wy;
    float r1 = p[y0 * W + x1] * (1.f - wy) + p[y1 * W + x1] * wy;
    float v = r0 * (1.f - wx) + r1 * wx;
    out[(((size_t)b * 128 + c) * Ho + yo) * Wo + xo] = v;
}

// ---------------- copy skip into concat buffer ch 64..127 ----------------
__global__ void copyskip_kernel(const float* __restrict__ skip, float* __restrict__ out, int H, int W)
{
    int total = B * 64 * H * W;
    int idx = blockIdx.x * blockDim.x + threadIdx.x;
    if (idx >= total) return;
    int hw = idx % (H * W);
    int c  = (idx / (H * W)) % 64;
    int b  = idx / (H * W * 64);
    out[(((size_t)b * 128 + 64 + c) * H) * W + hw] = skip[idx];
}

// ---------------- final 1x1 conv (64->2) + residual + NCHW->NHWC into d_out ----------------
__global__ void final_kernel(const float* __restrict__ in, const float* __restrict__ zf,
                             const float* __restrict__ wbuf, int woff, int boff,
                             float* __restrict__ out)
{
    __shared__ float sw[130];   // 2*64 weights + 2 biases
    int b  = blockIdx.y;
    int tid = threadIdx.x;
    const float* wb = wbuf + (size_t)b * OUTD;
    if (tid < 128) sw[tid] = wb[woff + tid];
    else if (tid < 130) sw[tid] = wb[boff + (tid - 128)];
    __syncthreads();
    int hw = blockIdx.x * 256 + tid;   // 256x256 = 65536 pixels
    const float* inb = in + (size_t)b * 64 * 65536 + hw;
    float a0 = sw[128], a1 = sw[129];
#pragma unroll 8
    for (int c = 0; c < 64; c++) {
        float v = inb[(size_t)c * 65536];
        a0 = fmaf(v, sw[c], a0);
        a1 = fmaf(v, sw[64 + c], a1);
    }
    size_t o = ((size_t)b * 65536 + hw) * 2;
    out[o]     = zf[o]     + a0;
    out[o + 1] = zf[o + 1] + a1;
}

// ---------------- host side ----------------
// flat layout offsets inside the 592002 vector (kernels then biases)
static const int KOFF[15] = {0, 1152, 38016, 74880, 111744, 148608, 185472, 222336,
                             259200, 332928, 369792, 443520, 480384, 554112, 590976};
static const int CINL[15] = {2, 64, 64, 64, 64, 64, 64, 64, 128, 64, 128, 64, 128, 64, 64};
#define BOFF(i) (591104 + 64 * (i))

static inline void launch_conv(const float* in, float* out, const float* wb,
                               int layer, int H, int relu)
{
    dim3 bs(16, 16);
    dim3 gs((H / 16) * (H / 16), 4, B);
    int cin = CINL[layer];
    if (cin == 2)
        conv3x3_kernel<2><<<gs, bs>>>(in, out, wb, KOFF[layer], BOFF(layer), H, H, relu);
    else if (cin == 64)
        conv3x3_kernel<64><<<gs, bs>>>(in, out, wb, KOFF[layer], BOFF(layer), H, H, relu);
    else
        conv3x3_kernel<128><<<gs, bs>>>(in, out, wb, KOFF[layer], BOFF(layer), H, H, relu);
}

extern "C" void kernel_launch(void* const* d_in, const int* in_sizes, int n_in,
                              void* d_out, int out_size)
{
    const float* zf = (const float*)d_in[0];
    /* d_in[1] = y, unused by the reference */
    const float* hp = (const float*)d_in[2];
    const float* W1 = (const float*)d_in[3];
    const float* b1 = (const float*)d_in[4];
    const float* W2 = (const float*)d_in[5];
    const float* b2 = (const float*)d_in[6];
    const float* Wo = (const float*)d_in[7];
    const float* bo = (const float*)d_in[8];
    float* out = (float*)d_out;
    float* l1 = out + (size_t)B * 256 * 256 * 2;   // 1048576

    float *pA, *pB, *pS1, *pS2, *pS3, *pW;
    cudaGetSymbolAddress((void**)&pA,  g_bufA);
    cudaGetSymbolAddress((void**)&pB,  g_bufB);
    cudaGetSymbolAddress((void**)&pS1, g_skip1);
    cudaGetSymbolAddress((void**)&pS2, g_skip2);
    cudaGetSymbolAddress((void**)&pS3, g_skip3);
    cudaGetSymbolAddress((void**)&pW,  g_w);

    // hypernet
    hyper1_kernel<<<1, 256>>>(hp, W1, b1, W2, b2);
    zero_l1_kernel<<<1, 32>>>(l1);
    weightgen_kernel<<<(OUTD + 255) / 256, 256>>>(Wo, bo, l1);

    // NHWC -> NCHW
    {
        int n = B * 2 * 256 * 256;
        transpose_in_kernel<<<(n + 255) / 256, 256>>>(zf, pB);
    }

    // encoder
    launch_conv(pB, pA, pW, 0, 256, 1);
    launch_conv(pA, pS1, pW, 1, 256, 1);      // conv1 (skip)
    { int n = B * 64 * 128 * 128; maxpool_kernel<<<(n + 255) / 256, 256>>>(pS1, pA, 256, 256); }
    launch_conv(pA, pB, pW, 2, 128, 1);
    launch_conv(pB, pS2, pW, 3, 128, 1);      // conv2 (skip)
    { int n = B * 64 * 64 * 64;   maxpool_kernel<<<(n + 255) / 256, 256>>>(pS2, pA, 128, 128); }
    launch_conv(pA, pB, pW, 4, 64, 1);
    launch_conv(pB, pS3, pW, 5, 64, 1);       // conv3 (skip)
    { int n = B * 64 * 32 * 32;   maxpool_kernel<<<(n + 255) / 256, 256>>>(pS3, pA, 64, 64); }
    launch_conv(pA, pB, pW, 6, 32, 1);
    launch_conv(pB, pA, pW, 7, 32, 1);        // conv4

    // decoder level 1 (32 -> 64)
    { int n = B * 64 * 64 * 64;   upsample_kernel<<<(n + 255) / 256, 256>>>(pA, pB, 32, 32); }
    { int n = B * 64 * 64 * 64;   copyskip_kernel<<<(n + 255) / 256, 256>>>(pS3, pB, 64, 64); }
    launch_conv(pB, pA, pW, 8, 64, 1);
    launch_conv(pA, pB, pW, 9, 64, 1);

    // decoder level 2 (64 -> 128)
    { int n = B * 64 * 128 * 128; upsample_kernel<<<(n + 255) / 256, 256>>>(pB, pA, 64, 64); }
    { int n = B * 64 * 128 * 128; copyskip_kernel<<<(n + 255) / 256, 256>>>(pS2, pA, 128, 128); }
    launch_conv(pA, pB, pW, 10, 128, 1);
    launch_conv(pB, pA, pW, 11, 128, 1);

    // decoder level 3 (128 -> 256)
    { int n = B * 64 * 256 * 256; upsample_kernel<<<(n + 255) / 256, 256>>>(pA, pB, 128, 128); }
    { int n = B * 64 * 256 * 256; copyskip_kernel<<<(n + 255) / 256, 256>>>(pS1, pB, 256, 256); }
    launch_conv(pB, pA, pW, 12, 256, 1);
    launch_conv(pA, pB, pW, 13, 256, 1);

    // 1x1 conv + residual + transpose into d_out
    {
        dim3 gs(65536 / 256, B);
        final_kernel<<<gs, 256>>>(pB, zf, pW, KOFF[14], BOFF(14), out);
    }
}

// round 2
// speedup vs baseline: 1.7830x; 1.7830x over previous
#include <cuda_runtime.h>
#include <math.h>

#define B 8
#define OUTD 592002

// ---------------- scratch (device globals; no allocation allowed) ----------------
__device__ float g_bufA[(size_t)B * 128 * 256 * 256];   // 268 MB ping
__device__ float g_bufB[(size_t)B * 128 * 256 * 256];   // 268 MB pong
__device__ float g_skip1[(size_t)B * 64 * 256 * 256];   // conv1 output
__device__ float g_skip2[(size_t)B * 64 * 128 * 128];   // conv2 output
__device__ float g_skip3[(size_t)B * 64 * 64 * 64];     // conv3 output
__device__ float g_w[(size_t)B * OUTD];                 // generated weights
__device__ float g_h2[B * 32];                          // hypernet hidden

// ---------------- f32x2 packed helpers ----------------
__device__ __forceinline__ void fma2(unsigned long long& acc, unsigned long long x,
                                     unsigned long long w)
{
    asm("fma.rn.f32x2 %0, %1, %2, %0;" : "+l"(acc) : "l"(x), "l"(w));
}
__device__ __forceinline__ unsigned long long pack2b(float a)
{
    unsigned long long r;
    asm("mov.b64 %0, {%1, %1};" : "=l"(r) : "f"(a));
    return r;
}
__device__ __forceinline__ float2 unpack2(unsigned long long v)
{
    float2 r;
    asm("mov.b64 {%0, %1}, %2;" : "=f"(r.x), "=f"(r.y) : "l"(v));
    return r;
}

// ---------------- hypernet stage 1: h2 = (hp@W1^T+b1)@W2^T+b2 ----------------
__global__ void hyper1_kernel(const float* __restrict__ hp, const float* __restrict__ W1,
                              const float* __restrict__ b1, const float* __restrict__ W2,
                              const float* __restrict__ b2)
{
    __shared__ float h1[B][32];
    int b = threadIdx.x >> 5;
    int i = threadIdx.x & 31;
    h1[b][i] = hp[b] * W1[i] + b1[i];   // IN_DIM = 1
    __syncthreads();
    float a = b2[i];
#pragma unroll
    for (int k = 0; k < 32; k++) a += h1[b][k] * W2[i * 32 + k];
    g_h2[b * 32 + i] = a;
}

__global__ void zero_l1_kernel(float* __restrict__ l1)
{
    if (threadIdx.x < B) l1[threadIdx.x] = 0.f;
}

// ---------------- hypernet stage 2: w = tanh(h2 @ Wo^T + bo), + L1 reduce ----------------
__global__ void weightgen_kernel(const float* __restrict__ Wo, const float* __restrict__ bo,
                                 float* __restrict__ l1out)
{
    __shared__ float sh2[B * 32];
    __shared__ float wsum[8][B];
    int tid = threadIdx.x;
    sh2[tid] = g_h2[tid];
    __syncthreads();

    int j = blockIdx.x * 256 + tid;
    float s[B];
#pragma unroll
    for (int b = 0; b < B; b++) s[b] = 0.f;

    if (j < OUTD) {
        float wr[32];
        const float* row = Wo + (size_t)j * 32;
#pragma unroll
        for (int i = 0; i < 32; i++) wr[i] = row[i];
        float bj = bo[j];
#pragma unroll
        for (int b = 0; b < B; b++) {
            float a = bj;
#pragma unroll
            for (int i = 0; i < 32; i++) a += wr[i] * sh2[b * 32 + i];
            float w = tanhf(a);
            g_w[(size_t)b * OUTD + j] = w;
            s[b] = fabsf(w);
        }
    }
    int warp = tid >> 5, lane = tid & 31;
#pragma unroll
    for (int b = 0; b < B; b++) {
        float v = s[b];
        for (int off = 16; off > 0; off >>= 1) v += __shfl_xor_sync(0xFFFFFFFFu, v, off);
        if (lane == 0) wsum[warp][b] = v;
    }
    __syncthreads();
    if (tid < B) {
        float a = 0.f;
#pragma unroll
        for (int w = 0; w < 8; w++) a += wsum[w][tid];
        atomicAdd(&l1out[tid], a);
    }
}

// ---------------- NHWC zf -> NCHW x0 ----------------
__global__ void transpose_in_kernel(const float* __restrict__ zf, float* __restrict__ out)
{
    int idx = blockIdx.x * blockDim.x + threadIdx.x;
    int total = B * 2 * 256 * 256;
    if (idx >= total) return;
    int w = idx & 255;
    int h = (idx >> 8) & 255;
    int c = (idx >> 16) & 1;
    int b = idx >> 17;
    out[idx] = zf[(((b * 256 + h) * 256 + w) << 1) + c];
}

// ---------------- 3x3 conv, pad=1, OC=64, per-sample weights ----------------
// Block: 256 threads, 32x32 spatial tile, 16 output channels.
// Each thread: 2x2 pixels x 16 oc; oc paired into f32x2 accumulators.
template<int CIN>
__global__ __launch_bounds__(256, 2) void conv3x3_kernel(
    const float* __restrict__ in, float* __restrict__ out,
    const float* __restrict__ wbuf, int woff, int boff, int H, int relu)
{
    constexpr int CS = (CIN < 4) ? CIN : 4;
    __shared__ float sIn[CS][34 * 34];
    __shared__ float2 sW[CS][8 * 9];      // (oc_even, oc_odd) pairs

    int b   = blockIdx.z;
    int OC0 = blockIdx.y * 16;
    int tiles = H >> 5;
    int ty0 = (blockIdx.x / tiles) << 5;
    int tx0 = (blockIdx.x % tiles) << 5;
    int tid = threadIdx.x;
    int tx = tid & 15, ty = tid >> 4;

    const float* wb  = wbuf + (size_t)b * OUTD;
    const float* inb = in + (size_t)b * CIN * H * H;

    unsigned long long acc[8][4];
#pragma unroll
    for (int i = 0; i < 8; i++)
#pragma unroll
        for (int p = 0; p < 4; p++) acc[i][p] = 0ull;

    for (int c0 = 0; c0 < CIN; c0 += CS) {
        __syncthreads();
        // stage CS input channels (34x34 haloed tiles)
        for (int idx = tid; idx < CS * 1156; idx += 256) {
            int cs = idx / 1156, rem = idx - cs * 1156;
            int r = rem / 34, cc = rem - r * 34;
            int gy = ty0 - 1 + r, gx = tx0 - 1 + cc;
            float v = 0.f;
            if ((unsigned)gy < (unsigned)H && (unsigned)gx < (unsigned)H)
                v = inb[(size_t)(c0 + cs) * H * H + gy * H + gx];
            sIn[cs][rem] = v;
        }
        // stage weights as oc-pairs
        for (int idx = tid; idx < CS * 72; idx += 256) {
            int cs = idx / 72, rem = idx - cs * 72;
            int ocp = rem / 9, k = rem - ocp * 9;
            const float* wp = wb + woff + ((size_t)(OC0 + 2 * ocp) * CIN + (c0 + cs)) * 9 + k;
            sW[cs][rem] = make_float2(wp[0], wp[CIN * 9]);
        }
        __syncthreads();

#pragma unroll
        for (int cs = 0; cs < CS; cs++) {
            float xi[16];
#pragma unroll
            for (int r = 0; r < 4; r++)
#pragma unroll
                for (int cc = 0; cc < 4; cc++)
                    xi[r * 4 + cc] = sIn[cs][(2 * ty + r) * 34 + 2 * tx + cc];
#pragma unroll
            for (int ky = 0; ky < 3; ky++)
#pragma unroll
                for (int kx = 0; kx < 3; kx++) {
                    unsigned long long xx[4];
#pragma unroll
                    for (int py = 0; py < 2; py++)
#pragma unroll
                        for (int px = 0; px < 2; px++)
                            xx[py * 2 + px] = pack2b(xi[(py + ky) * 4 + (px + kx)]);
#pragma unroll
                    for (int ocp = 0; ocp < 8; ocp++) {
                        unsigned long long w =
                            *reinterpret_cast<const unsigned long long*>(&sW[cs][ocp * 9 + ky * 3 + kx]);
#pragma unroll
                        for (int p = 0; p < 4; p++) fma2(acc[ocp][p], xx[p], w);
                    }
                }
        }
    }

    // epilogue: bias + relu + store
#pragma unroll
    for (int ocp = 0; ocp < 8; ocp++) {
        float b0 = wb[boff + OC0 + 2 * ocp];
        float b1 = wb[boff + OC0 + 2 * ocp + 1];
        float* o0 = out + (((size_t)b * 64 + OC0 + 2 * ocp) * H) * H;
        float* o1 = o0 + (size_t)H * H;
#pragma unroll
        for (int py = 0; py < 2; py++)
#pragma unroll
            for (int px = 0; px < 2; px++) {
                float2 v = unpack2(acc[ocp][py * 2 + px]);
                v.x += b0; v.y += b1;
                if (relu) { v.x = fmaxf(v.x, 0.f); v.y = fmaxf(v.y, 0.f); }
                int y = ty0 + 2 * ty + py, x = tx0 + 2 * tx + px;
                o0[y * H + x] = v.x;
                o1[y * H + x] = v.y;
            }
    }
}

// ---------------- 2x2 maxpool ----------------
__global__ void maxpool_kernel(const float* __restrict__ in, float* __restrict__ out, int H, int W)
{
    int Ho = H >> 1, Wo = W >> 1;
    int total = B * 64 * Ho * Wo;
    int idx = blockIdx.x * blockDim.x + threadIdx.x;
    if (idx >= total) return;
    int xo = idx % Wo;
    int yo = (idx / Wo) % Ho;
    int bc = idx / (Wo * Ho);
    const float* p = in + (size_t)bc * H * W + (yo * 2) * W + xo * 2;
    float v = fmaxf(fmaxf(p[0], p[1]), fmaxf(p[W], p[W + 1]));
    out[idx] = v;
}

// ---------------- bilinear upsample x2 (align_corners) -> concat ch 0..63 ----------------
__global__ void upsample_kernel(const float* __restrict__ in, float* __restrict__ out, int H, int W)
{
    int Ho = H * 2, Wo = W * 2;
    int total = B * 64 * Ho * Wo;
    int idx = blockIdx.x * blockDim.x + threadIdx.x;
    if (idx >= total) return;
    int xo = idx % Wo;
    int yo = (idx / Wo) % Ho;
    int c  = (idx / (Wo * Ho)) % 64;
    int b  = idx / (Wo * Ho * 64);

    float ys = (float)yo * (float)(H - 1) / (float)(Ho - 1);
    float xs = (float)xo * (float)(W - 1) / (float)(Wo - 1);
    int y0 = (int)floorf(ys); int y1 = min(y0 + 1, H - 1);
    int x0 = (int)floorf(xs); int x1 = min(x0 + 1, W - 1);
    float wy = ys - (float)y0, wx = xs - (float)x0;

    const float* p = in + ((size_t)b * 64 + c) * H * W;
    float r0 = p[y0 * W + x0] * (1.f - wy) + p[y1 * W + x0] * wy;
    float r1 = p[y0 * W + x1] * (1.f - wy) + p[y1 * W + x1] * wy;
    float v = r0 * (1.f - wx) + r1 * wx;
    out[(((size_t)b * 128 + c) * Ho + yo) * Wo + xo] = v;
}

// ---------------- copy skip into concat buffer ch 64..127 ----------------
__global__ void copyskip_kernel(const float* __restrict__ skip, float* __restrict__ out, int H, int W)
{
    int total = B * 64 * H * W;
    int idx = blockIdx.x * blockDim.x + threadIdx.x;
    if (idx >= total) return;
    int hw = idx % (H * W);
    int c  = (idx / (H * W)) % 64;
    int b  = idx / (H * W * 64);
    out[(((size_t)b * 128 + 64 + c) * H) * W + hw] = skip[idx];
}

// ---------------- final 1x1 conv (64->2) + residual + NCHW->NHWC ----------------
__global__ void final_kernel(const float* __restrict__ in, const float* __restrict__ zf,
                             const float* __restrict__ wbuf, int woff, int boff,
                             float* __restrict__ out)
{
    __shared__ float sw[130];
    int b  = blockIdx.y;
    int tid = threadIdx.x;
    const float* wb = wbuf + (size_t)b * OUTD;
    if (tid < 128) sw[tid] = wb[woff + tid];
    else if (tid < 130) sw[tid] = wb[boff + (tid - 128)];
    __syncthreads();
    int hw = blockIdx.x * 256 + tid;
    const float* inb = in + (size_t)b * 64 * 65536 + hw;
    float a0 = sw[128], a1 = sw[129];
#pragma unroll 8
    for (int c = 0; c < 64; c++) {
        float v = inb[(size_t)c * 65536];
        a0 = fmaf(v, sw[c], a0);
        a1 = fmaf(v, sw[64 + c], a1);
    }
    size_t o = ((size_t)b * 65536 + hw) * 2;
    out[o]     = zf[o]     + a0;
    out[o + 1] = zf[o + 1] + a1;
}

// ---------------- host side ----------------
static const int KOFF[15] = {0, 1152, 38016, 74880, 111744, 148608, 185472, 222336,
                             259200, 332928, 369792, 443520, 480384, 554112, 590976};
static const int CINL[15] = {2, 64, 64, 64, 64, 64, 64, 64, 128, 64, 128, 64, 128, 64, 64};
#define BOFF(i) (591104 + 64 * (i))

static inline void launch_conv(const float* in, float* out, const float* wb,
                               int layer, int H, int relu)
{
    dim3 gs((H / 32) * (H / 32), 4, B);
    int cin = CINL[layer];
    if (cin == 2)
        conv3x3_kernel<2><<<gs, 256>>>(in, out, wb, KOFF[layer], BOFF(layer), H, relu);
    else if (cin == 64)
        conv3x3_kernel<64><<<gs, 256>>>(in, out, wb, KOFF[layer], BOFF(layer), H, relu);
    else
        conv3x3_kernel<128><<<gs, 256>>>(in, out, wb, KOFF[layer], BOFF(layer), H, relu);
}

extern "C" void kernel_launch(void* const* d_in, const int* in_sizes, int n_in,
                              void* d_out, int out_size)
{
    const float* zf = (const float*)d_in[0];
    const float* hp = (const float*)d_in[2];
    const float* W1 = (const float*)d_in[3];
    const float* b1 = (const float*)d_in[4];
    const float* W2 = (const float*)d_in[5];
    const float* b2 = (const float*)d_in[6];
    const float* Wo = (const float*)d_in[7];
    const float* bo = (const float*)d_in[8];
    float* out = (float*)d_out;
    float* l1 = out + (size_t)B * 256 * 256 * 2;

    float *pA, *pB, *pS1, *pS2, *pS3, *pW;
    cudaGetSymbolAddress((void**)&pA,  g_bufA);
    cudaGetSymbolAddress((void**)&pB,  g_bufB);
    cudaGetSymbolAddress((void**)&pS1, g_skip1);
    cudaGetSymbolAddress((void**)&pS2, g_skip2);
    cudaGetSymbolAddress((void**)&pS3, g_skip3);
    cudaGetSymbolAddress((void**)&pW,  g_w);

    hyper1_kernel<<<1, 256>>>(hp, W1, b1, W2, b2);
    zero_l1_kernel<<<1, 32>>>(l1);
    weightgen_kernel<<<(OUTD + 255) / 256, 256>>>(Wo, bo, l1);

    {
        int n = B * 2 * 256 * 256;
        transpose_in_kernel<<<(n + 255) / 256, 256>>>(zf, pB);
    }

    // encoder
    launch_conv(pB, pA, pW, 0, 256, 1);
    launch_conv(pA, pS1, pW, 1, 256, 1);
    { int n = B * 64 * 128 * 128; maxpool_kernel<<<(n + 255) / 256, 256>>>(pS1, pA, 256, 256); }
    launch_conv(pA, pB, pW, 2, 128, 1);
    launch_conv(pB, pS2, pW, 3, 128, 1);
    { int n = B * 64 * 64 * 64;   maxpool_kernel<<<(n + 255) / 256, 256>>>(pS2, pA, 128, 128); }
    launch_conv(pA, pB, pW, 4, 64, 1);
    launch_conv(pB, pS3, pW, 5, 64, 1);
    { int n = B * 64 * 32 * 32;   maxpool_kernel<<<(n + 255) / 256, 256>>>(pS3, pA, 64, 64); }
    launch_conv(pA, pB, pW, 6, 32, 1);
    launch_conv(pB, pA, pW, 7, 32, 1);

    // decoder level 1 (32 -> 64)
    { int n = B * 64 * 64 * 64;   upsample_kernel<<<(n + 255) / 256, 256>>>(pA, pB, 32, 32); }
    { int n = B * 64 * 64 * 64;   copyskip_kernel<<<(n + 255) / 256, 256>>>(pS3, pB, 64, 64); }
    launch_conv(pB, pA, pW, 8, 64, 1);
    launch_conv(pA, pB, pW, 9, 64, 1);

    // decoder level 2 (64 -> 128)
    { int n = B * 64 * 128 * 128; upsample_kernel<<<(n + 255) / 256, 256>>>(pB, pA, 64, 64); }
    { int n = B * 64 * 128 * 128; copyskip_kernel<<<(n + 255) / 256, 256>>>(pS2, pA, 128, 128); }
    launch_conv(pA, pB, pW, 10, 128, 1);
    launch_conv(pB, pA, pW, 11, 128, 1);

    // decoder level 3 (128 -> 256)
    { int n = B * 64 * 256 * 256; upsample_kernel<<<(n + 255) / 256, 256>>>(pA, pB, 128, 128); }
    { int n = B * 64 * 256 * 256; copyskip_kernel<<<(n + 255) / 256, 256>>>(pS1, pB, 256, 256); }
    launch_conv(pB, pA, pW, 12, 256, 1);
    launch_conv(pA, pB, pW, 13, 256, 1);

    {
        dim3 gs(65536 / 256, B);
        final_kernel<<<gs, 256>>>(pB, zf, pW, KOFF[14], BOFF(14), out);
    }
}